// round 10
// baseline (speedup 1.0000x reference)
#include <cuda_runtime.h>
#include <cuda_fp16.h>

// PairwisePotential1 — column-strip streaming, stride-4 half2 pairing.
// Thread owns 8 cols (strip) x 8 output rows; pixel pairs are (p, p+4) so every
// pack is (v_m, v_m+4) = one F2FP, no PRMT. Rows stream with 3-buffer rotation.
// first = 1 + sum_{8 fwd offsets} exp2(-(s*diff)^2 + L), s = sqrt(0.5*log2e),
// L = K*d, K = -0.5*log2(e), d in {1, sqrt2}. Zero padding.
// out = w1 * first/9 + w2 * (4+4*sqrt2)/9.

#define S 128
#define SS (S * S)
#define FULLM 0xFFFFFFFFu

struct Pk { __half2 p[6]; };   // (v_m, v_{m+4}), m = 0..5 ; v_0/v_9 are halo

__device__ __forceinline__ __half2 eterm(__half2 cs, __half2 n,
                                         __half2 LL, __half2 Sn) {
    __half2 ds = __hfma2(n, Sn, cs);                 // s*(c - n)
    return h2exp2(__hfma2(__hneg2(ds), ds, LL));     // exp2(L - ds^2)
}

__device__ __forceinline__ void loadrow(Pk& P, const float* rp, bool valid, int sl) {
    float4 A = make_float4(0.f, 0.f, 0.f, 0.f);
    float4 B = make_float4(0.f, 0.f, 0.f, 0.f);
    if (valid) { A = *(const float4*)rp; B = *(const float4*)(rp + 4); }
    float v0 = __shfl_up_sync(FULLM, B.w, 1, 16);    // col base-1 from left lane
    float v9 = __shfl_down_sync(FULLM, A.x, 1, 16);  // col base+8 from right lane
    if (sl == 0)  v0 = 0.f;
    if (sl == 15) v9 = 0.f;
    P.p[0] = __floats2half2_rn(v0,  A.w);
    P.p[1] = __floats2half2_rn(A.x, B.x);
    P.p[2] = __floats2half2_rn(A.y, B.y);
    P.p[3] = __floats2half2_rn(A.z, B.z);
    P.p[4] = __floats2half2_rn(A.w, B.w);
    P.p[5] = __floats2half2_rn(B.x, v9);
}

__device__ __forceinline__ void step(const Pk& A, const Pk& B, const Pk& C,
                                     const float* w1p, const float* w2p, float* op,
                                     __half2 Sp, __half2 Sn, __half2 L1h, __half2 L2h,
                                     __half2 ONEh) {
    float f[8];
#pragma unroll
    for (int p = 0; p < 4; p++) {
        __half2 cs = __hmul2(Sp, A.p[p]);            // prescaled centers
        __half2 a = __hadd2(ONEh, eterm(cs, A.p[p + 1], L1h, Sn));
        a = __hadd2(a, eterm(cs, A.p[p + 2], L1h, Sn));
        a = __hadd2(a, eterm(cs, B.p[p],     L1h, Sn));
        a = __hadd2(a, eterm(cs, C.p[p],     L1h, Sn));
        __half2 b =    eterm(cs, B.p[p + 1], L2h, Sn);
        b = __hadd2(b, eterm(cs, B.p[p + 2], L2h, Sn));
        b = __hadd2(b, eterm(cs, C.p[p + 1], L2h, Sn));
        b = __hadd2(b, eterm(cs, C.p[p + 2], L2h, Sn));
        float2 ff = __half22float2(__hadd2(a, b));
        f[p] = ff.x; f[p + 4] = ff.y;                // pair lanes are px p, p+4
    }
    const float INV9   = 1.0f / 9.0f;
    const float SECOND = (4.0f + 4.0f * 1.41421356237309504880f) / 9.0f;
    float4 w1a = *(const float4*)w1p,       w1b = *(const float4*)(w1p + 4);
    float4 w2a = *(const float4*)w2p,       w2b = *(const float4*)(w2p + 4);
    float4 o0, o1;
    o0.x = fmaf(w1a.x, f[0] * INV9, w2a.x * SECOND);
    o0.y = fmaf(w1a.y, f[1] * INV9, w2a.y * SECOND);
    o0.z = fmaf(w1a.z, f[2] * INV9, w2a.z * SECOND);
    o0.w = fmaf(w1a.w, f[3] * INV9, w2a.w * SECOND);
    o1.x = fmaf(w1b.x, f[4] * INV9, w2b.x * SECOND);
    o1.y = fmaf(w1b.y, f[5] * INV9, w2b.y * SECOND);
    o1.z = fmaf(w1b.z, f[6] * INV9, w2b.z * SECOND);
    o1.w = fmaf(w1b.w, f[7] * INV9, w2b.w * SECOND);
    *(float4*)op       = o0;
    *(float4*)(op + 4) = o1;
}

__global__ __launch_bounds__(256) void pp_kernel(
    const float* __restrict__ x,
    const float* __restrict__ w1,
    const float* __restrict__ w2,
    float* __restrict__ out)
{
    int t  = blockIdx.x * blockDim.x + threadIdx.x;
    int sl = threadIdx.x & 15;          // strip lane within 16-wide shuffle segment
    int g  = (t >> 4) & 15;             // rowgroup: rows 8g .. 8g+7
    int bc = t >> 8;                    // b*C + c
    int c  = bc & 63;
    int x0 = sl << 3;                   // column base (8 cols per thread)
    int r0 = g << 3;

    const float Kf = -0.5f * 1.44269504088896340736f;
    const float sF = 0.84933300468f;                       // sqrt(0.5*log2e)
    const __half2 Sp  = __float2half2_rn(sF);
    const __half2 Sn  = __float2half2_rn(-sF);
    const __half2 L1h = __float2half2_rn(Kf);                            // d=1
    const __half2 L2h = __float2half2_rn(Kf * 1.41421356237309504880f);  // d=sqrt2
    const __half2 ONEh = __float2half2_rn(1.0f);

    const float* xbase = x   + (size_t)bc * SS + r0 * S + x0;
    const float* w1p   = w1  + (size_t)c  * SS + r0 * S + x0;
    const float* w2p   = w2  + (size_t)c  * SS + r0 * S + x0;
    float*       op    = out + (size_t)bc * SS + r0 * S + x0;

    Pk P0, P1, P2;
    loadrow(P0, xbase - S,     (g > 0), sl);   // row r0-1 (zero for g==0)
    loadrow(P1, xbase,         true,    sl);   // row r0
    loadrow(P2, xbase + S,     true,    sl);   // row r0+1 (always < 128)

#define ST(A,B,C,K) step(A, B, C, w1p + (K)*S, w2p + (K)*S, op + (K)*S, \
                         Sp, Sn, L1h, L2h, ONEh);

    ST(P0, P1, P2, 0)
    loadrow(P0, xbase + 2 * S, true, sl);  ST(P1, P2, P0, 1)
    loadrow(P1, xbase + 3 * S, true, sl);  ST(P2, P0, P1, 2)
    loadrow(P2, xbase + 4 * S, true, sl);  ST(P0, P1, P2, 3)
    loadrow(P0, xbase + 5 * S, true, sl);  ST(P1, P2, P0, 4)
    loadrow(P1, xbase + 6 * S, true, sl);  ST(P2, P0, P1, 5)
    loadrow(P2, xbase + 7 * S, true, sl);  ST(P0, P1, P2, 6)
    loadrow(P0, xbase + 8 * S, (g < 15), sl);  ST(P1, P2, P0, 7)
#undef ST
}

extern "C" void kernel_launch(void* const* d_in, const int* in_sizes, int n_in,
                              void* d_out, int out_size)
{
    const float* x  = (const float*)d_in[0];
    const float* w1 = (const float*)d_in[1];
    const float* w2 = (const float*)d_in[2];
    float* out = (float*)d_out;

    // 8 cols x 8 rows = 64 px per thread-slot: threads = B*C*16 strips*16 rowgroups
    int total = out_size >> 6;
    int threads = 256;
    int blocks = (total + threads - 1) / threads;
    pp_kernel<<<blocks, threads>>>(x, w1, w2, out);
}

// round 11
// speedup vs baseline: 1.0077x; 1.0077x over previous
#include <cuda_runtime.h>
#include <cuda_fp16.h>

// PairwisePotential1 — column-strip streaming, stride-4 half2 pairing,
// 8 cols x 4 rows per thread (balance instr economy vs occupancy/waves).
// Pixel pairs are (p, p+4): every pack is (v_m, v_m+4) = one F2FP, no PRMT.
// first = 1 + sum_{8 fwd offsets} exp2(-(s*diff)^2 + L), s = sqrt(0.5*log2e),
// L = K*d, K = -0.5*log2(e), d in {1, sqrt2}. Zero padding.
// out = w1 * first/9 + w2 * (4+4*sqrt2)/9.

#define S 128
#define SS (S * S)
#define FULLM 0xFFFFFFFFu

struct Pk { __half2 p[6]; };   // (v_m, v_{m+4}), m = 0..5 ; v_0/v_9 are halo

__device__ __forceinline__ __half2 eterm(__half2 cs, __half2 n,
                                         __half2 LL, __half2 Sn) {
    __half2 ds = __hfma2(n, Sn, cs);                 // s*(c - n)
    return h2exp2(__hfma2(__hneg2(ds), ds, LL));     // exp2(L - ds^2)
}

__device__ __forceinline__ void loadrow(Pk& P, const float* rp, bool valid, int sl) {
    float4 A = make_float4(0.f, 0.f, 0.f, 0.f);
    float4 B = make_float4(0.f, 0.f, 0.f, 0.f);
    if (valid) { A = *(const float4*)rp; B = *(const float4*)(rp + 4); }
    float v0 = __shfl_up_sync(FULLM, B.w, 1, 16);    // col base-1 from left lane
    float v9 = __shfl_down_sync(FULLM, A.x, 1, 16);  // col base+8 from right lane
    if (sl == 0)  v0 = 0.f;
    if (sl == 15) v9 = 0.f;
    P.p[0] = __floats2half2_rn(v0,  A.w);
    P.p[1] = __floats2half2_rn(A.x, B.x);
    P.p[2] = __floats2half2_rn(A.y, B.y);
    P.p[3] = __floats2half2_rn(A.z, B.z);
    P.p[4] = __floats2half2_rn(A.w, B.w);
    P.p[5] = __floats2half2_rn(B.x, v9);
}

__device__ __forceinline__ void step(const Pk& A, const Pk& B, const Pk& C,
                                     const float* w1p, const float* w2p, float* op,
                                     __half2 Sp, __half2 Sn, __half2 L1h, __half2 L2h,
                                     __half2 ONEh) {
    float f[8];
#pragma unroll
    for (int p = 0; p < 4; p++) {
        __half2 cs = __hmul2(Sp, A.p[p]);            // prescaled centers
        __half2 a = __hadd2(ONEh, eterm(cs, A.p[p + 1], L1h, Sn));
        a = __hadd2(a, eterm(cs, A.p[p + 2], L1h, Sn));
        a = __hadd2(a, eterm(cs, B.p[p],     L1h, Sn));
        a = __hadd2(a, eterm(cs, C.p[p],     L1h, Sn));
        __half2 b =    eterm(cs, B.p[p + 1], L2h, Sn);
        b = __hadd2(b, eterm(cs, B.p[p + 2], L2h, Sn));
        b = __hadd2(b, eterm(cs, C.p[p + 1], L2h, Sn));
        b = __hadd2(b, eterm(cs, C.p[p + 2], L2h, Sn));
        float2 ff = __half22float2(__hadd2(a, b));
        f[p] = ff.x; f[p + 4] = ff.y;                // pair lanes are px p, p+4
    }
    const float INV9   = 1.0f / 9.0f;
    const float SECOND = (4.0f + 4.0f * 1.41421356237309504880f) / 9.0f;
    float4 w1a = *(const float4*)w1p,       w1b = *(const float4*)(w1p + 4);
    float4 w2a = *(const float4*)w2p,       w2b = *(const float4*)(w2p + 4);
    float4 o0, o1;
    o0.x = fmaf(w1a.x, f[0] * INV9, w2a.x * SECOND);
    o0.y = fmaf(w1a.y, f[1] * INV9, w2a.y * SECOND);
    o0.z = fmaf(w1a.z, f[2] * INV9, w2a.z * SECOND);
    o0.w = fmaf(w1a.w, f[3] * INV9, w2a.w * SECOND);
    o1.x = fmaf(w1b.x, f[4] * INV9, w2b.x * SECOND);
    o1.y = fmaf(w1b.y, f[5] * INV9, w2b.y * SECOND);
    o1.z = fmaf(w1b.z, f[6] * INV9, w2b.z * SECOND);
    o1.w = fmaf(w1b.w, f[7] * INV9, w2b.w * SECOND);
    *(float4*)op       = o0;
    *(float4*)(op + 4) = o1;
}

__global__ __launch_bounds__(256) void pp_kernel(
    const float* __restrict__ x,
    const float* __restrict__ w1,
    const float* __restrict__ w2,
    float* __restrict__ out)
{
    int t  = blockIdx.x * blockDim.x + threadIdx.x;
    int sl = threadIdx.x & 15;          // strip lane within 16-wide shuffle segment
    int g  = (t >> 4) & 31;             // rowgroup: rows 4g .. 4g+3
    int bc = t >> 9;                    // b*C + c
    int c  = bc & 63;
    int x0 = sl << 3;                   // column base (8 cols per thread)
    int r0 = g << 2;

    const float Kf = -0.5f * 1.44269504088896340736f;
    const float sF = 0.84933300468f;                       // sqrt(0.5*log2e)
    const __half2 Sp  = __float2half2_rn(sF);
    const __half2 Sn  = __float2half2_rn(-sF);
    const __half2 L1h = __float2half2_rn(Kf);                            // d=1
    const __half2 L2h = __float2half2_rn(Kf * 1.41421356237309504880f);  // d=sqrt2
    const __half2 ONEh = __float2half2_rn(1.0f);

    const float* xbase = x   + (size_t)bc * SS + r0 * S + x0;
    const float* w1p   = w1  + (size_t)c  * SS + r0 * S + x0;
    const float* w2p   = w2  + (size_t)c  * SS + r0 * S + x0;
    float*       op    = out + (size_t)bc * SS + r0 * S + x0;

    Pk P0, P1, P2;
    loadrow(P0, xbase - S,     (g > 0), sl);   // row r0-1 (zero for g==0)
    loadrow(P1, xbase,         true,    sl);   // row r0
    loadrow(P2, xbase + S,     true,    sl);   // row r0+1 (r0+1 <= 125)

#define ST(A,B,C,K) step(A, B, C, w1p + (K)*S, w2p + (K)*S, op + (K)*S, \
                         Sp, Sn, L1h, L2h, ONEh);

    ST(P0, P1, P2, 0)
    loadrow(P0, xbase + 2 * S, true, sl);          ST(P1, P2, P0, 1)
    loadrow(P1, xbase + 3 * S, true, sl);          ST(P2, P0, P1, 2)
    loadrow(P2, xbase + 4 * S, (g < 31), sl);      ST(P0, P1, P2, 3)
#undef ST
}

extern "C" void kernel_launch(void* const* d_in, const int* in_sizes, int n_in,
                              void* d_out, int out_size)
{
    const float* x  = (const float*)d_in[0];
    const float* w1 = (const float*)d_in[1];
    const float* w2 = (const float*)d_in[2];
    float* out = (float*)d_out;

    // 8 cols x 4 rows = 32 px per thread
    int total = out_size >> 5;
    int threads = 256;
    int blocks = (total + threads - 1) / threads;
    pp_kernel<<<blocks, threads>>>(x, w1, w2, out);
}